// round 8
// baseline (speedup 1.0000x reference)
#include <cuda_runtime.h>
#include <math.h>

#define N 8192
#define D 64
#define ALPHA 0.2f
#define NB 4096          // value bins
#define CAP 64           // member-list capacity per bin (avg occupancy = 2)
#define NBCH 64          // scan chunks
#define BCH 64           // bins per chunk

// ---------------- scratch ----------------
__device__ float g_h[N * D];
__device__ float g_f1[N];
__device__ float g_f2[N];
__device__ float g_fmin, g_fmax, g_scale;
__device__ float g_binP[NB * D];      // sum of p_j * h_j over bin
__device__ float g_binQ[NB * D];      // sum of q_j * h_j over bin
__device__ float g_bDp[NB], g_bDq[NB];
__device__ int   g_cnt[NB];
__device__ int   g_mIdx[NB * CAP];
__device__ float g_mF2[NB * CAP];
__device__ float g_mP[NB * CAP];      // member p (precomputed exp)
__device__ float g_mQ[NB * CAP];      // member q
__device__ float g_csumP[NBCH * D], g_csumQ[NBCH * D];
__device__ float g_csp[NBCH], g_csq[NBCH];
__device__ float g_Cpos[(NB + 1) * D];   // inclusive suffix of binP
__device__ float g_Cneg[(NB + 1) * D];   // exclusive prefix of binQ
__device__ float g_Dpos[NB + 1], g_Dneg[NB + 1];

// monotone-encoded float extrema
__device__ unsigned g_encmax = 0u;
__device__ unsigned g_encmin = 0xFFFFFFFFu;

// grid barrier counters for the fused agg+scan kernel (self-resetting)
__device__ int g_c1 = 0;
__device__ int g_c2 = 0;
__device__ int g_cdone = 0;

__device__ __forceinline__ int bin_of(float v, float fmin, float scale) {
    int b = (int)((v - fmin) * scale);
    return b < 0 ? 0 : (b > NB - 1 ? NB - 1 : b);
}
__device__ __forceinline__ unsigned enc_f(float f) {
    unsigned u = __float_as_uint(f);
    return (u & 0x80000000u) ? ~u : (u | 0x80000000u);
}
__device__ __forceinline__ float dec_f(unsigned e) {
    return (e & 0x80000000u) ? __uint_as_float(e & 0x7FFFFFFFu) : __uint_as_float(~e);
}

// =============== K1: feat + zero bin scratch + extrema ===============
// 128 blocks x 1024 threads, 64 rows/block
__global__ void k_feat(const float* __restrict__ x, const float* __restrict__ Wt,
                       const float* __restrict__ a1, const float* __restrict__ b1,
                       const float* __restrict__ a2, const float* __restrict__ b2) {
    __shared__ float sW[D * D];
    __shared__ float sx[16 * D];
    __shared__ float s12[64];

    int t = threadIdx.x;
    int row_base = blockIdx.x * 64;

    // zero this block's slice of bin scratch (consumed next kernel)
    {
        float4 z = make_float4(0.f, 0.f, 0.f, 0.f);
        if (t < 512) {
            ((float4*)g_binP)[blockIdx.x * 512 + t] = z;
            ((float4*)g_binQ)[blockIdx.x * 512 + t] = z;
        }
        if (t < 32) {
            int i = blockIdx.x * 32 + t;
            g_cnt[i] = 0; g_bDp[i] = 0.f; g_bDq[i] = 0.f;
        }
    }

    // ---------------- feat ----------------
    {
        int r = t >> 6;              // 0..15
        int o = t & 63;
#pragma unroll
        for (int u = 0; u < 4; u++) sW[t + u * 1024] = Wt[t + u * 1024];
        float A1 = a1[o], A2 = a2[o];
        float B1 = b1[0], B2 = b2[0];

        float xv = x[(row_base + r) * D + o];

        for (int it = 0; it < 4; it++) {
            int row = row_base + it * 16 + r;
            __syncthreads();
            sx[r * 64 + o] = xv;
            __syncthreads();
            if (it < 3) xv = x[(row + 16) * D + o];

            float h = 0.f;
#pragma unroll
            for (int i = 0; i < D; i++) h = fmaf(sx[r * 64 + i], sW[i * 64 + o], h);
            g_h[row * D + o] = h;

            float v1 = h * A1;
            float v2 = h * A2;
#pragma unroll
            for (int s = 16; s; s >>= 1) {
                v1 += __shfl_xor_sync(0xFFFFFFFFu, v1, s);
                v2 += __shfl_xor_sync(0xFFFFFFFFu, v2, s);
            }
            int w = t >> 5;
            if ((t & 31) == 0) { s12[w] = v1; s12[32 + w] = v2; }
            __syncthreads();
            if (o == 0) {
                g_f1[row] = s12[2 * r] + s12[2 * r + 1] + B1;
                g_f2[row] = s12[32 + 2 * r] + s12[32 + 2 * r + 1] + B2;
            }
        }
    }
    __syncthreads();

    // extrema of this block's 64 f2 values (exact, order-independent)
    if (t < 64) {
        float v = g_f2[row_base + t];
        float mx = v, mn = v;
#pragma unroll
        for (int s = 16; s; s >>= 1) {
            mx = fmaxf(mx, __shfl_xor_sync(0xFFFFFFFFu, mx, s));
            mn = fminf(mn, __shfl_xor_sync(0xFFFFFFFFu, mn, s));
        }
        if ((t & 31) == 0) {
            atomicMax(&g_encmax, enc_f(mx));
            atomicMin(&g_encmin, enc_f(mn));
        }
    }
}

// =============== K2: bin aggregation + barrier + bin-level scan (fused) ===============
// 64 blocks x 256 threads; dyn smem = (2*BCH*64 + 2*BCH)*4 = 33.3 KB
__global__ void k_aggscan() {
    extern __shared__ float sm2[];
    float* sBP = sm2;                       // BCH*64
    float* sBQ = sm2 + BCH * 64;
    float* sdp = sm2 + 2 * BCH * 64;        // BCH
    float* sdq = sdp + BCH;
    __shared__ int sbin[128];
    __shared__ float sp[128], sq[128];
    __shared__ float scons[4];
    __shared__ float sP[4][64], sQ[4][64], sw[8];

    int t = threadIdx.x;

    // ---- phase A: per-bin atomic aggregation (128 nodes/block) ----
    if (t == 0) {
        float fmax = dec_f(g_encmax);
        float fmin = dec_f(g_encmin);
        float scale = (float)NB / fmaxf(fmax - fmin, 1e-20f);
        scons[0] = fmin; scons[1] = fmax; scons[2] = scale;
        if (blockIdx.x == 0) { g_fmin = fmin; g_fmax = fmax; g_scale = scale; }
    }
    __syncthreads();
    float fmin = scons[0], fmax = scons[1], scale = scons[2];

    int node0 = blockIdx.x * 128;
    if (t < 128) {
        int node = node0 + t;
        float f2 = g_f2[node];
        int b = bin_of(f2, fmin, scale);
        float d = f2 - fmax;
        float pv = expf(d), qv = expf(ALPHA * d);
        sbin[t] = b; sp[t] = pv; sq[t] = qv;
        atomicAdd(&g_bDp[b], pv);
        atomicAdd(&g_bDq[b], qv);
        int c = atomicAdd(&g_cnt[b], 1);
        if (c < CAP) {
            g_mIdx[b * CAP + c] = node;
            g_mF2[b * CAP + c] = f2;
            g_mP[b * CAP + c] = pv;
            g_mQ[b * CAP + c] = qv;
        }
    }
    __syncthreads();

    int o = t & 63, r = t >> 6;
#pragma unroll 8
    for (int m = r; m < 128; m += 4) {
        float hv = g_h[(node0 + m) * D + o];          // coalesced (original order)
        atomicAdd(&g_binP[sbin[m] * D + o], sp[m] * hv);
        atomicAdd(&g_binQ[sbin[m] * D + o], sq[m] * hv);
    }

    // ---- barrier 1: all bin atomics done ----
    __syncthreads();
    __threadfence();
    if (t == 0) {
        atomicAdd(&g_c1, 1);
        while (atomicAdd(&g_c1, 0) < 64) __nanosleep(64);
        if (blockIdx.x == 0) {                       // extrema consumed; reset for replay
            atomicExch(&g_encmax, 0u);
            atomicExch(&g_encmin, 0xFFFFFFFFu);
        }
    }
    __syncthreads();

    // ---- phase B: stage chunk bins + chunk sums ----
    int chunk = blockIdx.x;
    int b0 = chunk * BCH;
    {
        const float4* srcP = (const float4*)(g_binP + (size_t)b0 * D);
        const float4* srcQ = (const float4*)(g_binQ + (size_t)b0 * D);
        float4* dP = (float4*)sBP;
        float4* dQ = (float4*)sBQ;
#pragma unroll
        for (int i = t; i < BCH * 16; i += 256) { dP[i] = __ldcg(&srcP[i]); dQ[i] = __ldcg(&srcQ[i]); }
        if (t < BCH) { sdp[t] = __ldcg(&g_bDp[b0 + t]); sdq[t] = __ldcg(&g_bDq[b0 + t]); }
    }
    __syncthreads();

    float aP = 0.f, aQ = 0.f;
#pragma unroll
    for (int m = r; m < BCH; m += 4) { aP += sBP[m * 64 + o]; aQ += sBQ[m * 64 + o]; }
    sP[r][o] = aP; sQ[r][o] = aQ;

    float spv = 0.f, sqv = 0.f;
    if (t < BCH) { spv = sdp[t]; sqv = sdq[t]; }
#pragma unroll
    for (int s = 16; s; s >>= 1) {
        spv += __shfl_xor_sync(0xFFFFFFFFu, spv, s);
        sqv += __shfl_xor_sync(0xFFFFFFFFu, sqv, s);
    }
    if (t < BCH && (t & 31) == 0) { sw[t >> 5] = spv; sw[4 + (t >> 5)] = sqv; }
    __syncthreads();

    if (r == 0) {
        g_csumP[chunk * 64 + o] = sP[0][o] + sP[1][o] + sP[2][o] + sP[3][o];
        g_csumQ[chunk * 64 + o] = sQ[0][o] + sQ[1][o] + sQ[2][o] + sQ[3][o];
    }
    if (t == 0) {
        g_csp[chunk] = sw[0] + sw[1];
        g_csq[chunk] = sw[4] + sw[5];
    }

    // ---- barrier 2: all chunk sums done ----
    __syncthreads();
    __threadfence();
    if (t == 0) {
        atomicAdd(&g_c2, 1);
        while (atomicAdd(&g_c2, 0) < 64) __nanosleep(64);
    }
    __syncthreads();

    // ---- phase C: walks ----
    if (t < 64) {
        float off = 0.f;
#pragma unroll
        for (int c = 0; c < NBCH; c++) {
            float v = __ldcg(&g_csumQ[c * 64 + t]);
            if (c < chunk) off += v;
        }
        float run = off;
#pragma unroll 8
        for (int m = 0; m < BCH; m++) {
            g_Cneg[(size_t)(b0 + m) * D + t] = run;
            run += sBQ[m * 64 + t];
        }
        if (chunk == NBCH - 1) g_Cneg[(size_t)NB * D + t] = run;
    } else if (t < 128) {
        int c0 = t - 64;
        float off = 0.f;
#pragma unroll
        for (int c = 0; c < NBCH; c++) {
            float v = __ldcg(&g_csumP[c * 64 + c0]);
            if (c > chunk) off += v;
        }
        float run = off;
        if (chunk == NBCH - 1) g_Cpos[(size_t)NB * D + c0] = 0.f;
#pragma unroll 8
        for (int m = BCH - 1; m >= 0; m--) {
            run += sBP[m * 64 + c0];
            g_Cpos[(size_t)(b0 + m) * D + c0] = run;
        }
    } else if (t == 128) {
        float off = 0.f;
#pragma unroll
        for (int c = 0; c < NBCH; c++) { float v = __ldcg(&g_csq[c]); if (c < chunk) off += v; }
        float run = off;
        for (int m = 0; m < BCH; m++) { g_Dneg[b0 + m] = run; run += sdq[m]; }
        if (chunk == NBCH - 1) g_Dneg[NB] = run;
    } else if (t == 129) {
        float off = 0.f;
#pragma unroll
        for (int c = 0; c < NBCH; c++) { float v = __ldcg(&g_csp[c]); if (c > chunk) off += v; }
        float run = off;
        if (chunk == NBCH - 1) g_Dpos[NB] = 0.f;
        for (int m = BCH - 1; m >= 0; m--) { run += sdp[m]; g_Dpos[b0 + m] = run; }
    }

    // ---- replay-safe counter reset (last block out) ----
    __syncthreads();
    if (t == 0) {
        int d = atomicAdd(&g_cdone, 1);
        if (d == 63) {
            atomicExch(&g_c1, 0);
            atomicExch(&g_c2, 0);
            atomicExch(&g_cdone, 0);
        }
    }
}

// =============== K3: per-row combine + exact boundary bin + ELU ===============
__global__ void k_out(float* __restrict__ out) {
    int t = threadIdx.x;                 // 256, 4 rows/block
    int row = blockIdx.x * 4 + (t >> 6);
    int o = t & 63;

    float f1 = g_f1[row];
    float fmax = g_fmax, fmin = g_fmin, scale = g_scale;
    float s0 = f1 + fmax;
    // single-exp row factors: m = max(s0, a*s0)
    float e = expf(-(1.0f - ALPHA) * fabsf(s0));
    float A = (s0 >= 0.f) ? 1.0f : e;
    float B = (s0 >= 0.f) ? e : 1.0f;
    float thr = -f1;

    int b = bin_of(thr, fmin, scale);

    float num = A * g_Cpos[(size_t)(b + 1) * D + o] + B * g_Cneg[(size_t)b * D + o];
    float den = A * g_Dpos[b + 1] + B * g_Dneg[b];

    int cnt = g_cnt[b];
    if (cnt > CAP) cnt = CAP;
    for (int j = 0; j < cnt; j++) {      // exact compares within boundary bin
        int idx = g_mIdx[b * CAP + j];
        float f2j = g_mF2[b * CAP + j];
        float hv = g_h[idx * D + o];
        float w = (f2j >= thr) ? A * g_mP[b * CAP + j] : B * g_mQ[b * CAP + j];
        num = fmaf(w, hv, num); den += w;
    }

    float ret = num / den;
    out[row * D + o] = (ret > 0.f) ? ret : expm1f(ret);
}

// ---------------- launch ----------------
extern "C" void kernel_launch(void* const* d_in, const int* in_sizes, int n_in,
                              void* d_out, int out_size) {
    const float* x  = (const float*)d_in[0];
    const float* Wt = (const float*)d_in[1];
    const float* a1 = (const float*)d_in[2];
    const float* b1 = (const float*)d_in[3];
    const float* a2 = (const float*)d_in[4];
    const float* b2 = (const float*)d_in[5];
    float* out = (float*)d_out;

    const int smem_scan = (2 * BCH * 64 + 2 * BCH) * 4;   // 33.3 KB

    static bool attr_set = false;
    if (!attr_set) {
        cudaFuncSetAttribute(k_aggscan, cudaFuncAttributeMaxDynamicSharedMemorySize, smem_scan);
        attr_set = true;
    }

    k_feat<<<128, 1024>>>(x, Wt, a1, b1, a2, b2);
    k_aggscan<<<64, 256, smem_scan>>>();
    k_out<<<2048, 256>>>(out);
}

// round 9
// speedup vs baseline: 1.1798x; 1.1798x over previous
#include <cuda_runtime.h>
#include <math.h>

#define N 8192
#define D 64
#define ALPHA 0.2f
#define NB 4096          // value bins
#define CAP 64           // member-list capacity per bin
#define NBCH 32          // scan chunks
#define BCH 128          // bins per chunk

// ---------------- scratch ----------------
__device__ float g_h[N * D];
__device__ float g_f1[N];
__device__ float g_f2[N];
__device__ float g_fmin, g_fmax, g_scale;
__device__ float g_binP[NB * D];      // sum of p_j * h_j over bin
__device__ float g_binQ[NB * D];      // sum of q_j * h_j over bin
__device__ float g_bDp[NB], g_bDq[NB];
__device__ int   g_cnt[NB];
__device__ int   g_mIdx[NB * CAP];
__device__ float g_mF2[NB * CAP];
__device__ float g_mP[NB * CAP];      // member p (precomputed exp)
__device__ float g_mQ[NB * CAP];      // member q
__device__ float g_csumP[NBCH * D], g_csumQ[NBCH * D];
__device__ float g_csp[NBCH], g_csq[NBCH];
__device__ float g_Cpos[(NB + 1) * D];   // inclusive suffix of binP
__device__ float g_Cneg[(NB + 1) * D];   // exclusive prefix of binQ
__device__ float g_Dpos[NB + 1], g_Dneg[NB + 1];

// monotone-encoded float extrema (reset in k_binscan after consumption)
__device__ unsigned g_encmax = 0u;
__device__ unsigned g_encmin = 0xFFFFFFFFu;

// scan barrier (self-resetting)
__device__ int g_c2 = 0;
__device__ int g_c2done = 0;

__device__ __forceinline__ int bin_of(float v, float fmin, float scale) {
    int b = (int)((v - fmin) * scale);
    return b < 0 ? 0 : (b > NB - 1 ? NB - 1 : b);
}
__device__ __forceinline__ unsigned enc_f(float f) {
    unsigned u = __float_as_uint(f);
    return (u & 0x80000000u) ? ~u : (u | 0x80000000u);
}
__device__ __forceinline__ float dec_f(unsigned e) {
    return (e & 0x80000000u) ? __uint_as_float(e & 0x7FFFFFFFu) : __uint_as_float(~e);
}

// =============== K1: feat (1x4 register tiling) + zero scratch + extrema ===============
// 128 blocks x 1024 threads, 64 rows/block; thread -> row (t>>4), cols 4*(t&15)..+3
__global__ void k_feat(const float* __restrict__ x, const float* __restrict__ Wt,
                       const float* __restrict__ a1, const float* __restrict__ b1,
                       const float* __restrict__ a2, const float* __restrict__ b2) {
    __shared__ float sW[D * D];
    __shared__ float sx[64 * D];

    int t = threadIdx.x;
    int row_base = blockIdx.x * 64;
    int r = t >> 4;              // 0..63 local row
    int og = (t & 15) * 4;       // output col group
    int row = row_base + r;

    // zero this block's slice of bin scratch
    {
        float4 z = make_float4(0.f, 0.f, 0.f, 0.f);
        if (t < 512) {
            ((float4*)g_binP)[blockIdx.x * 512 + t] = z;
            ((float4*)g_binQ)[blockIdx.x * 512 + t] = z;
        }
        if (t < 32) {
            int i = blockIdx.x * 32 + t;
            g_cnt[i] = 0; g_bDp[i] = 0.f; g_bDq[i] = 0.f;
        }
    }

    // load W (4096 floats) and the block's 64 x rows (one shot)
#pragma unroll
    for (int u = 0; u < 4; u++) sW[t + u * 1024] = Wt[t + u * 1024];
    *(float4*)&sx[r * 64 + og] = *(const float4*)&x[row * D + og];
    __syncthreads();

    // h[row][og..og+3] = sum_i x[row][i] * W[i][og..og+3]
    float4 h = make_float4(0.f, 0.f, 0.f, 0.f);
#pragma unroll
    for (int i = 0; i < D; i++) {
        float xv = sx[r * 64 + i];                       // broadcast within 16 lanes
        float4 w = *(const float4*)&sW[i * 64 + og];     // LDS.128
        h.x = fmaf(xv, w.x, h.x);
        h.y = fmaf(xv, w.y, h.y);
        h.z = fmaf(xv, w.z, h.z);
        h.w = fmaf(xv, w.w, h.w);
    }
    *(float4*)&g_h[row * D + og] = h;

    // f1 = h . a1 + b1, f2 = h . a2 + b2 (reduce over 16 lanes)
    float4 va1 = *(const float4*)&a1[og];
    float4 va2 = *(const float4*)&a2[og];
    float v1 = h.x * va1.x + h.y * va1.y + h.z * va1.z + h.w * va1.w;
    float v2 = h.x * va2.x + h.y * va2.y + h.z * va2.z + h.w * va2.w;
#pragma unroll
    for (int s = 8; s; s >>= 1) {
        v1 += __shfl_xor_sync(0xFFFFFFFFu, v1, s);
        v2 += __shfl_xor_sync(0xFFFFFFFFu, v2, s);
    }
    if ((t & 15) == 0) {
        g_f1[row] = v1 + b1[0];
        g_f2[row] = v2 + b2[0];
    }
    __syncthreads();

    // extrema of this block's 64 f2 values (exact, order-independent)
    if (t < 64) {
        float v = g_f2[row_base + t];
        float mx = v, mn = v;
#pragma unroll
        for (int s = 16; s; s >>= 1) {
            mx = fmaxf(mx, __shfl_xor_sync(0xFFFFFFFFu, mx, s));
            mn = fminf(mn, __shfl_xor_sync(0xFFFFFFFFu, mn, s));
        }
        if ((t & 31) == 0) {
            atomicMax(&g_encmax, enc_f(mx));
            atomicMin(&g_encmin, enc_f(mn));
        }
    }
}

// =============== K2: per-bin atomic aggregation ===============
// 64 blocks x 256 threads, 128 nodes/block
__global__ void k_binagg() {
    __shared__ int sbin[128];
    __shared__ float sp[128], sq[128];
    __shared__ float scons[4];

    int t = threadIdx.x;
    if (t == 0) {
        float fmax = dec_f(g_encmax);     // final after K1 (kernel boundary)
        float fmin = dec_f(g_encmin);
        float scale = (float)NB / fmaxf(fmax - fmin, 1e-20f);
        scons[0] = fmin; scons[1] = fmax; scons[2] = scale;
        if (blockIdx.x == 0) { g_fmin = fmin; g_fmax = fmax; g_scale = scale; }
    }
    __syncthreads();
    float fmin = scons[0], fmax = scons[1], scale = scons[2];

    int node0 = blockIdx.x * 128;
    if (t < 128) {
        int node = node0 + t;
        float f2 = g_f2[node];
        int b = bin_of(f2, fmin, scale);
        float d = f2 - fmax;
        float pv = expf(d), qv = expf(ALPHA * d);
        sbin[t] = b; sp[t] = pv; sq[t] = qv;
        atomicAdd(&g_bDp[b], pv);
        atomicAdd(&g_bDq[b], qv);
        int c = atomicAdd(&g_cnt[b], 1);
        if (c < CAP) {
            g_mIdx[b * CAP + c] = node;
            g_mF2[b * CAP + c] = f2;
            g_mP[b * CAP + c] = pv;
            g_mQ[b * CAP + c] = qv;
        }
    }
    __syncthreads();

    int o = t & 63, r = t >> 6;
#pragma unroll 8
    for (int m = r; m < 128; m += 4) {
        float hv = g_h[(node0 + m) * D + o];          // coalesced (original order)
        atomicAdd(&g_binP[sbin[m] * D + o], sp[m] * hv);
        atomicAdd(&g_binQ[sbin[m] * D + o], sq[m] * hv);
    }
}

// =============== K3: bin-level prefix/suffix scan (smem-staged, fused) ===============
// NBCH=32 blocks x 256 threads; dyn smem = 2*BCH*64*4 + 2*BCH*4 = 66.5 KB
__global__ void k_binscan() {
    extern __shared__ float sm2[];
    float* sBP = sm2;                       // BCH*64
    float* sBQ = sm2 + BCH * 64;
    float* sdp = sm2 + 2 * BCH * 64;        // BCH
    float* sdq = sdp + BCH;
    __shared__ float sP[4][64], sQ[4][64], sw[8];

    int t = threadIdx.x;
    int chunk = blockIdx.x;
    int b0 = chunk * BCH;

    if (chunk == 0 && t == 0) {             // extrema consumed by K2; reset for replay
        atomicExch(&g_encmax, 0u);
        atomicExch(&g_encmin, 0xFFFFFFFFu);
    }

    // stage this chunk's bin aggregates (coalesced float4, high MLP)
    {
        const float4* srcP = (const float4*)(g_binP + (size_t)b0 * D);
        const float4* srcQ = (const float4*)(g_binQ + (size_t)b0 * D);
        float4* dP = (float4*)sBP;
        float4* dQ = (float4*)sBQ;
#pragma unroll
        for (int i = t; i < BCH * 16; i += 256) { dP[i] = __ldcg(&srcP[i]); dQ[i] = __ldcg(&srcQ[i]); }
        if (t < BCH) { sdp[t] = __ldcg(&g_bDp[b0 + t]); sdq[t] = __ldcg(&g_bDq[b0 + t]); }
    }
    __syncthreads();

    // chunk sums
    int o = t & 63, r = t >> 6;
    float aP = 0.f, aQ = 0.f;
#pragma unroll 8
    for (int m = r; m < BCH; m += 4) { aP += sBP[m * 64 + o]; aQ += sBQ[m * 64 + o]; }
    sP[r][o] = aP; sQ[r][o] = aQ;

    float spv = 0.f, sqv = 0.f;
    if (t < BCH) { spv = sdp[t]; sqv = sdq[t]; }
#pragma unroll
    for (int s = 16; s; s >>= 1) {
        spv += __shfl_xor_sync(0xFFFFFFFFu, spv, s);
        sqv += __shfl_xor_sync(0xFFFFFFFFu, sqv, s);
    }
    if (t < BCH && (t & 31) == 0) { sw[t >> 5] = spv; sw[4 + (t >> 5)] = sqv; }
    __syncthreads();

    if (r == 0) {
        g_csumP[chunk * 64 + o] = sP[0][o] + sP[1][o] + sP[2][o] + sP[3][o];
        g_csumQ[chunk * 64 + o] = sQ[0][o] + sQ[1][o] + sQ[2][o] + sQ[3][o];
    }
    if (t == 0) {
        g_csp[chunk] = sw[0] + sw[1] + sw[2] + sw[3];
        g_csq[chunk] = sw[4] + sw[5] + sw[6] + sw[7];
    }

    // grid barrier (32 blocks, all resident)
    __syncthreads();
    __threadfence();
    if (t == 0) {
        atomicAdd(&g_c2, 1);
        while (atomicAdd(&g_c2, 0) < NBCH) __nanosleep(64);
    }
    __syncthreads();

    // walks
    if (t < 64) {
        float off = 0.f;
#pragma unroll
        for (int c = 0; c < NBCH; c++) {
            float v = __ldcg(&g_csumQ[c * 64 + t]);
            if (c < chunk) off += v;
        }
        float run = off;
#pragma unroll 8
        for (int m = 0; m < BCH; m++) {
            g_Cneg[(size_t)(b0 + m) * D + t] = run;
            run += sBQ[m * 64 + t];
        }
        if (chunk == NBCH - 1) g_Cneg[(size_t)NB * D + t] = run;
    } else if (t < 128) {
        int c0 = t - 64;
        float off = 0.f;
#pragma unroll
        for (int c = 0; c < NBCH; c++) {
            float v = __ldcg(&g_csumP[c * 64 + c0]);
            if (c > chunk) off += v;
        }
        float run = off;
        if (chunk == NBCH - 1) g_Cpos[(size_t)NB * D + c0] = 0.f;
#pragma unroll 8
        for (int m = BCH - 1; m >= 0; m--) {
            run += sBP[m * 64 + c0];
            g_Cpos[(size_t)(b0 + m) * D + c0] = run;
        }
    } else if (t == 128) {
        float off = 0.f;
#pragma unroll
        for (int c = 0; c < NBCH; c++) { float v = __ldcg(&g_csq[c]); if (c < chunk) off += v; }
        float run = off;
        for (int m = 0; m < BCH; m++) { g_Dneg[b0 + m] = run; run += sdq[m]; }
        if (chunk == NBCH - 1) g_Dneg[NB] = run;
    } else if (t == 129) {
        float off = 0.f;
#pragma unroll
        for (int c = 0; c < NBCH; c++) { float v = __ldcg(&g_csp[c]); if (c > chunk) off += v; }
        float run = off;
        if (chunk == NBCH - 1) g_Dpos[NB] = 0.f;
        for (int m = BCH - 1; m >= 0; m--) { run += sdp[m]; g_Dpos[b0 + m] = run; }
    }

    // replay-safe counter reset
    __syncthreads();
    if (t == 0) {
        int d = atomicAdd(&g_c2done, 1);
        if (d == NBCH - 1) { atomicExch(&g_c2, 0); atomicExch(&g_c2done, 0); }
    }
}

// =============== K4: per-row combine + exact boundary bin + ELU ===============
__global__ void k_out(float* __restrict__ out) {
    int t = threadIdx.x;                 // 256, 4 rows/block
    int row = blockIdx.x * 4 + (t >> 6);
    int o = t & 63;

    float f1 = g_f1[row];
    float fmax = g_fmax, fmin = g_fmin, scale = g_scale;
    float s0 = f1 + fmax;
    // single-exp row factors (m = max(s0, a*s0)): e = exp(-(1-a)|s0|)
    float e = expf(-(1.0f - ALPHA) * fabsf(s0));
    float A = (s0 >= 0.f) ? 1.0f : e;
    float B = (s0 >= 0.f) ? e : 1.0f;
    float thr = -f1;

    int b = bin_of(thr, fmin, scale);

    float num = A * g_Cpos[(size_t)(b + 1) * D + o] + B * g_Cneg[(size_t)b * D + o];
    float den = A * g_Dpos[b + 1] + B * g_Dneg[b];

    int cnt = g_cnt[b];
    if (cnt > CAP) cnt = CAP;
    for (int j = 0; j < cnt; j++) {      // exact compares within boundary bin
        int idx = g_mIdx[b * CAP + j];
        float f2j = g_mF2[b * CAP + j];
        float hv = g_h[idx * D + o];
        float w = (f2j >= thr) ? A * g_mP[b * CAP + j] : B * g_mQ[b * CAP + j];
        num = fmaf(w, hv, num); den += w;
    }

    float ret = num / den;
    out[row * D + o] = (ret > 0.f) ? ret : expm1f(ret);
}

// ---------------- launch ----------------
extern "C" void kernel_launch(void* const* d_in, const int* in_sizes, int n_in,
                              void* d_out, int out_size) {
    const float* x  = (const float*)d_in[0];
    const float* Wt = (const float*)d_in[1];
    const float* a1 = (const float*)d_in[2];
    const float* b1 = (const float*)d_in[3];
    const float* a2 = (const float*)d_in[4];
    const float* b2 = (const float*)d_in[5];
    float* out = (float*)d_out;

    const int smem_scan = (2 * BCH * 64 + 2 * BCH) * 4;   // 66.5 KB

    static bool attr_set = false;
    if (!attr_set) {
        cudaFuncSetAttribute(k_binscan, cudaFuncAttributeMaxDynamicSharedMemorySize, smem_scan);
        attr_set = true;
    }

    k_feat<<<128, 1024>>>(x, Wt, a1, b1, a2, b2);
    k_binagg<<<64, 256>>>();
    k_binscan<<<NBCH, 256, smem_scan>>>();
    k_out<<<2048, 256>>>(out);
}

// round 11
// speedup vs baseline: 1.4119x; 1.1967x over previous
#include <cuda_runtime.h>
#include <math.h>

#define N 8192
#define D 64
#define ALPHA 0.2f
#define NB 4096          // value bins
#define CAP 64           // member-list capacity per bin
#define NBCH 32          // scan chunks
#define BCH 128          // bins per chunk

// ---------------- scratch ----------------
__device__ float g_h[N * D];
__device__ float g_f1[N];
__device__ float g_f2[N];
__device__ float g_fmin, g_fmax, g_scale;
__device__ float g_binP[NB * D];      // sum of p_j * h_j over bin
__device__ float g_binQ[NB * D];      // sum of q_j * h_j over bin
__device__ float g_bDp[NB], g_bDq[NB];
__device__ int   g_cnt[NB];
__device__ int   g_mIdx[NB * CAP];
__device__ float g_mF2[NB * CAP];
__device__ float g_mP[NB * CAP];      // member p (precomputed exp)
__device__ float g_mQ[NB * CAP];      // member q
__device__ float g_csumP[NBCH * D], g_csumQ[NBCH * D];
__device__ float g_csp[NBCH], g_csq[NBCH];
__device__ float g_Cpos[(NB + 1) * D];   // inclusive suffix of binP
__device__ float g_Cneg[(NB + 1) * D];   // exclusive prefix of binQ
__device__ float g_Dpos[NB + 1], g_Dneg[NB + 1];

// monotone-encoded float extrema (reset in k_binscan after consumption)
__device__ unsigned g_encmax = 0u;
__device__ unsigned g_encmin = 0xFFFFFFFFu;

// scan barrier (self-resetting)
__device__ int g_c2 = 0;
__device__ int g_c2done = 0;

__device__ __forceinline__ int bin_of(float v, float fmin, float scale) {
    int b = (int)((v - fmin) * scale);
    return b < 0 ? 0 : (b > NB - 1 ? NB - 1 : b);
}
__device__ __forceinline__ unsigned enc_f(float f) {
    unsigned u = __float_as_uint(f);
    return (u & 0x80000000u) ? ~u : (u | 0x80000000u);
}
__device__ __forceinline__ float dec_f(unsigned e) {
    return (e & 0x80000000u) ? __uint_as_float(e & 0x7FFFFFFFu) : __uint_as_float(~e);
}

// =============== K1: feat (1x4 register tiling) + zero scratch + extrema ===============
// 128 blocks x 1024 threads, 64 rows/block; thread -> row (t>>4), cols 4*(t&15)..+3
__global__ void k_feat(const float* __restrict__ x, const float* __restrict__ Wt,
                       const float* __restrict__ a1, const float* __restrict__ b1,
                       const float* __restrict__ a2, const float* __restrict__ b2) {
    __shared__ float sW[D * D];
    __shared__ float sx[64 * D];

    int t = threadIdx.x;
    int row_base = blockIdx.x * 64;
    int r = t >> 4;              // 0..63 local row
    int og = (t & 15) * 4;       // output col group
    int row = row_base + r;

    // zero this block's slice of bin scratch
    {
        float4 z = make_float4(0.f, 0.f, 0.f, 0.f);
        if (t < 512) {
            ((float4*)g_binP)[blockIdx.x * 512 + t] = z;
            ((float4*)g_binQ)[blockIdx.x * 512 + t] = z;
        }
        if (t < 32) {
            int i = blockIdx.x * 32 + t;
            g_cnt[i] = 0; g_bDp[i] = 0.f; g_bDq[i] = 0.f;
        }
    }

    // load W (4096 floats) and the block's 64 x rows (one shot)
#pragma unroll
    for (int u = 0; u < 4; u++) sW[t + u * 1024] = Wt[t + u * 1024];
    *(float4*)&sx[r * 64 + og] = *(const float4*)&x[row * D + og];
    __syncthreads();

    // h[row][og..og+3] = sum_i x[row][i] * W[i][og..og+3]
    float4 h = make_float4(0.f, 0.f, 0.f, 0.f);
#pragma unroll
    for (int i = 0; i < D; i++) {
        float xv = sx[r * 64 + i];                       // broadcast within 16 lanes
        float4 w = *(const float4*)&sW[i * 64 + og];     // LDS.128
        h.x = fmaf(xv, w.x, h.x);
        h.y = fmaf(xv, w.y, h.y);
        h.z = fmaf(xv, w.z, h.z);
        h.w = fmaf(xv, w.w, h.w);
    }
    *(float4*)&g_h[row * D + og] = h;

    // f1 = h . a1 + b1, f2 = h . a2 + b2 (reduce over 16 lanes)
    float4 va1 = *(const float4*)&a1[og];
    float4 va2 = *(const float4*)&a2[og];
    float v1 = h.x * va1.x + h.y * va1.y + h.z * va1.z + h.w * va1.w;
    float v2 = h.x * va2.x + h.y * va2.y + h.z * va2.z + h.w * va2.w;
#pragma unroll
    for (int s = 8; s; s >>= 1) {
        v1 += __shfl_xor_sync(0xFFFFFFFFu, v1, s);
        v2 += __shfl_xor_sync(0xFFFFFFFFu, v2, s);
    }
    if ((t & 15) == 0) {
        g_f1[row] = v1 + b1[0];
        g_f2[row] = v2 + b2[0];
    }
    __syncthreads();

    // extrema of this block's 64 f2 values (exact, order-independent)
    if (t < 64) {
        float v = g_f2[row_base + t];
        float mx = v, mn = v;
#pragma unroll
        for (int s = 16; s; s >>= 1) {
            mx = fmaxf(mx, __shfl_xor_sync(0xFFFFFFFFu, mx, s));
            mn = fminf(mn, __shfl_xor_sync(0xFFFFFFFFu, mn, s));
        }
        if ((t & 31) == 0) {
            atomicMax(&g_encmax, enc_f(mx));
            atomicMin(&g_encmin, enc_f(mn));
        }
    }
}

// =============== K2: per-bin atomic aggregation (float4 RED) ===============
// 64 blocks x 256 threads, 128 nodes/block
__global__ void k_binagg() {
    __shared__ int sbin[128];
    __shared__ float sp[128], sq[128];
    __shared__ float scons[4];

    int t = threadIdx.x;
    if (t == 0) {
        float fmax = dec_f(g_encmax);     // final after K1 (kernel boundary)
        float fmin = dec_f(g_encmin);
        float scale = (float)NB / fmaxf(fmax - fmin, 1e-20f);
        scons[0] = fmin; scons[1] = fmax; scons[2] = scale;
        if (blockIdx.x == 0) { g_fmin = fmin; g_fmax = fmax; g_scale = scale; }
    }
    __syncthreads();
    float fmin = scons[0], fmax = scons[1], scale = scons[2];

    int node0 = blockIdx.x * 128;
    if (t < 128) {
        int node = node0 + t;
        float f2 = g_f2[node];
        int b = bin_of(f2, fmin, scale);
        float d = f2 - fmax;
        float pv = expf(d), qv = expf(ALPHA * d);
        sbin[t] = b; sp[t] = pv; sq[t] = qv;
        atomicAdd(&g_bDp[b], pv);
        atomicAdd(&g_bDq[b], qv);
        int c = atomicAdd(&g_cnt[b], 1);
        if (c < CAP) {
            g_mIdx[b * CAP + c] = node;
            g_mF2[b * CAP + c] = f2;
            g_mP[b * CAP + c] = pv;
            g_mQ[b * CAP + c] = qv;
        }
    }
    __syncthreads();

    // 16 threads per node row; float4 loads + float4 atomics (sm_90+)
    int og = (t & 15) * 4;
    int rr = t >> 4;                     // 0..15
#pragma unroll
    for (int m = rr; m < 128; m += 16) {
        float4 hv = *(const float4*)&g_h[(node0 + m) * D + og];   // LDG.128 coalesced
        int b = sbin[m];
        float pv = sp[m], qv = sq[m];
        atomicAdd((float4*)&g_binP[b * D + og],
                  make_float4(pv * hv.x, pv * hv.y, pv * hv.z, pv * hv.w));
        atomicAdd((float4*)&g_binQ[b * D + og],
                  make_float4(qv * hv.x, qv * hv.y, qv * hv.z, qv * hv.w));
    }
}

// =============== K3: bin-level prefix/suffix scan (smem-staged, fused) ===============
// NBCH=32 blocks x 256 threads; dyn smem = 2*BCH*64*4 + 2*BCH*4 = 66.5 KB
__global__ void k_binscan() {
    extern __shared__ float sm2[];
    float* sBP = sm2;                       // BCH*64
    float* sBQ = sm2 + BCH * 64;
    float* sdp = sm2 + 2 * BCH * 64;        // BCH
    float* sdq = sdp + BCH;
    __shared__ float sP[4][64], sQ[4][64], sw[8];

    int t = threadIdx.x;
    int chunk = blockIdx.x;
    int b0 = chunk * BCH;

    if (chunk == 0 && t == 0) {             // extrema consumed by K2; reset for replay
        atomicExch(&g_encmax, 0u);
        atomicExch(&g_encmin, 0xFFFFFFFFu);
    }

    // stage this chunk's bin aggregates (coalesced float4, high MLP)
    {
        const float4* srcP = (const float4*)(g_binP + (size_t)b0 * D);
        const float4* srcQ = (const float4*)(g_binQ + (size_t)b0 * D);
        float4* dP = (float4*)sBP;
        float4* dQ = (float4*)sBQ;
#pragma unroll
        for (int i = t; i < BCH * 16; i += 256) { dP[i] = __ldcg(&srcP[i]); dQ[i] = __ldcg(&srcQ[i]); }
        if (t < BCH) { sdp[t] = __ldcg(&g_bDp[b0 + t]); sdq[t] = __ldcg(&g_bDq[b0 + t]); }
    }
    __syncthreads();

    // chunk sums
    int o = t & 63, r = t >> 6;
    float aP = 0.f, aQ = 0.f;
#pragma unroll 8
    for (int m = r; m < BCH; m += 4) { aP += sBP[m * 64 + o]; aQ += sBQ[m * 64 + o]; }
    sP[r][o] = aP; sQ[r][o] = aQ;

    float spv = 0.f, sqv = 0.f;
    if (t < BCH) { spv = sdp[t]; sqv = sdq[t]; }
#pragma unroll
    for (int s = 16; s; s >>= 1) {
        spv += __shfl_xor_sync(0xFFFFFFFFu, spv, s);
        sqv += __shfl_xor_sync(0xFFFFFFFFu, sqv, s);
    }
    if (t < BCH && (t & 31) == 0) { sw[t >> 5] = spv; sw[4 + (t >> 5)] = sqv; }
    __syncthreads();

    if (r == 0) {
        g_csumP[chunk * 64 + o] = sP[0][o] + sP[1][o] + sP[2][o] + sP[3][o];
        g_csumQ[chunk * 64 + o] = sQ[0][o] + sQ[1][o] + sQ[2][o] + sQ[3][o];
    }
    if (t == 0) {
        g_csp[chunk] = sw[0] + sw[1] + sw[2] + sw[3];
        g_csq[chunk] = sw[4] + sw[5] + sw[6] + sw[7];
    }

    // grid barrier (32 blocks, all resident)
    __syncthreads();
    __threadfence();
    if (t == 0) {
        atomicAdd(&g_c2, 1);
        while (atomicAdd(&g_c2, 0) < NBCH) __nanosleep(64);
    }
    __syncthreads();

    // walks
    if (t < 64) {
        float off = 0.f;
#pragma unroll
        for (int c = 0; c < NBCH; c++) {
            float v = __ldcg(&g_csumQ[c * 64 + t]);
            if (c < chunk) off += v;
        }
        float run = off;
#pragma unroll 8
        for (int m = 0; m < BCH; m++) {
            g_Cneg[(size_t)(b0 + m) * D + t] = run;
            run += sBQ[m * 64 + t];
        }
        if (chunk == NBCH - 1) g_Cneg[(size_t)NB * D + t] = run;
    } else if (t < 128) {
        int c0 = t - 64;
        float off = 0.f;
#pragma unroll
        for (int c = 0; c < NBCH; c++) {
            float v = __ldcg(&g_csumP[c * 64 + c0]);
            if (c > chunk) off += v;
        }
        float run = off;
        if (chunk == NBCH - 1) g_Cpos[(size_t)NB * D + c0] = 0.f;
#pragma unroll 8
        for (int m = BCH - 1; m >= 0; m--) {
            run += sBP[m * 64 + c0];
            g_Cpos[(size_t)(b0 + m) * D + c0] = run;
        }
    } else if (t == 128) {
        float off = 0.f;
#pragma unroll
        for (int c = 0; c < NBCH; c++) { float v = __ldcg(&g_csq[c]); if (c < chunk) off += v; }
        float run = off;
        for (int m = 0; m < BCH; m++) { g_Dneg[b0 + m] = run; run += sdq[m]; }
        if (chunk == NBCH - 1) g_Dneg[NB] = run;
    } else if (t == 129) {
        float off = 0.f;
#pragma unroll
        for (int c = 0; c < NBCH; c++) { float v = __ldcg(&g_csp[c]); if (c > chunk) off += v; }
        float run = off;
        if (chunk == NBCH - 1) g_Dpos[NB] = 0.f;
        for (int m = BCH - 1; m >= 0; m--) { run += sdp[m]; g_Dpos[b0 + m] = run; }
    }

    // replay-safe counter reset
    __syncthreads();
    if (t == 0) {
        int d = atomicAdd(&g_c2done, 1);
        if (d == NBCH - 1) { atomicExch(&g_c2, 0); atomicExch(&g_c2done, 0); }
    }
}

// =============== K4: per-row combine + boundary bin + ELU (1x4 tiled) ===============
// 512 blocks x 256 threads; 16 rows/block, 16 threads/row, float4 columns
__global__ void k_out(float* __restrict__ out) {
    int t = threadIdx.x;
    int row = blockIdx.x * 16 + (t >> 4);
    int og = (t & 15) * 4;

    float f1 = g_f1[row];
    float fmax = g_fmax, fmin = g_fmin, scale = g_scale;
    float s0 = f1 + fmax;
    // single-exp row factors (m = max(s0, a*s0)): e = exp(-(1-a)|s0|)
    float e = expf(-(1.0f - ALPHA) * fabsf(s0));
    float A = (s0 >= 0.f) ? 1.0f : e;
    float B = (s0 >= 0.f) ? e : 1.0f;
    float thr = -f1;

    int b = bin_of(thr, fmin, scale);

    float4 cp = *(const float4*)&g_Cpos[(size_t)(b + 1) * D + og];
    float4 cn = *(const float4*)&g_Cneg[(size_t)b * D + og];
    float4 num = make_float4(A * cp.x + B * cn.x, A * cp.y + B * cn.y,
                             A * cp.z + B * cn.z, A * cp.w + B * cn.w);
    float den = A * g_Dpos[b + 1] + B * g_Dneg[b];

    int cnt = g_cnt[b];
    if (cnt > CAP) cnt = CAP;
    for (int j = 0; j < cnt; j++) {      // exact compares within boundary bin
        int idx = g_mIdx[b * CAP + j];           // broadcast loads within 16 lanes
        float f2j = g_mF2[b * CAP + j];
        float4 hv = *(const float4*)&g_h[(size_t)idx * D + og];
        float w = (f2j >= thr) ? A * g_mP[b * CAP + j] : B * g_mQ[b * CAP + j];
        num.x = fmaf(w, hv.x, num.x);
        num.y = fmaf(w, hv.y, num.y);
        num.z = fmaf(w, hv.z, num.z);
        num.w = fmaf(w, hv.w, num.w);
        den += w;
    }

    float inv = 1.0f / den;
    float4 ret = make_float4(num.x * inv, num.y * inv, num.z * inv, num.w * inv);
    float4 o4;
    o4.x = (ret.x > 0.f) ? ret.x : expm1f(ret.x);
    o4.y = (ret.y > 0.f) ? ret.y : expm1f(ret.y);
    o4.z = (ret.z > 0.f) ? ret.z : expm1f(ret.z);
    o4.w = (ret.w > 0.f) ? ret.w : expm1f(ret.w);
    *(float4*)&out[(size_t)row * D + og] = o4;
}

// ---------------- launch ----------------
extern "C" void kernel_launch(void* const* d_in, const int* in_sizes, int n_in,
                              void* d_out, int out_size) {
    const float* x  = (const float*)d_in[0];
    const float* Wt = (const float*)d_in[1];
    const float* a1 = (const float*)d_in[2];
    const float* b1 = (const float*)d_in[3];
    const float* a2 = (const float*)d_in[4];
    const float* b2 = (const float*)d_in[5];
    float* out = (float*)d_out;

    const int smem_scan = (2 * BCH * 64 + 2 * BCH) * 4;   // 66.5 KB

    static bool attr_set = false;
    if (!attr_set) {
        cudaFuncSetAttribute(k_binscan, cudaFuncAttributeMaxDynamicSharedMemorySize, smem_scan);
        attr_set = true;
    }

    k_feat<<<128, 1024>>>(x, Wt, a1, b1, a2, b2);
    k_binagg<<<64, 256>>>();
    k_binscan<<<NBCH, 256, smem_scan>>>();
    k_out<<<512, 256>>>(out);
}